// round 16
// baseline (speedup 1.0000x reference)
#include <cuda_runtime.h>

#define TPB 512
#define NBLK 296                      // prep: 2 CTAs/SM, all co-resident
#define BITEMS 4
#define BTILE 2048
#define AITEMS 4
#define ATILE 2048
#define MAX_BOND (1 << 22)
#define MAX_ATOM (1 << 20)
#define MAX_BT (MAX_BOND / BTILE)
#define MAX_AT0 (MAX_ATOM / ATILE)
#define CUTOFF 0.8f

#define EMIT_TPB 256
#define EMIT_NBLK 896
#define ATE 128                       // atoms per emission tile
#define LUCAP 24576                   // task-lookup capacity (tasks)

// ---------------- scratch (static device globals; no allocations) ----------
__device__ int g_deg[MAX_ATOM];
__device__ int2 g_ab[MAX_ATOM];       // {bondOff, deg}
__device__ int g_triStart[MAX_ATOM];
__device__ float g_keptF[MAX_BOND];
__device__ unsigned long long g_mask[MAX_BOND / 64];
__device__ int g_tileCnt[MAX_BT];
__device__ int g_tileOff[MAX_BT];
__device__ unsigned long long g_atPack[MAX_AT0];
__device__ unsigned long long g_atPackOff[MAX_AT0];
__device__ int g_T;
__device__ int g_bound[260];
__device__ volatile int g_barArrive;
__device__ volatile unsigned g_barGen;

// ---------------- helpers ---------------------------------------------------
__device__ __forceinline__ void gridBarrier() {
    __syncthreads();
    if (threadIdx.x == 0) {
        __threadfence();
        unsigned gen = g_barGen;
        if (atomicAdd((int*)&g_barArrive, 1) == NBLK - 1) {
            g_barArrive = 0;
            __threadfence();
            g_barGen = gen + 1;
        } else {
            while (g_barGen == gen) __nanosleep(64);
        }
        __threadfence();
    }
    __syncthreads();
}

template <typename T>
__device__ __forceinline__ T warpIncl(T v) {
#pragma unroll
    for (int d = 1; d < 32; d <<= 1) {
        T n = __shfl_up_sync(0xffffffffu, v, d);
        if ((threadIdx.x & 31) >= d) v += n;
    }
    return v;
}

template <typename T>
__device__ __forceinline__ T blockExcl(T v, T* smem, T* total) {
    int lane = threadIdx.x & 31, w = threadIdx.x >> 5, nw = blockDim.x >> 5;
    T inc = warpIncl(v);
    if (lane == 31) smem[w] = inc;
    __syncthreads();
    if (w == 0) {
        T x = (lane < nw) ? smem[lane] : (T)0;
        T xi = warpIncl(x);
        if (lane < nw) smem[lane] = xi - x;
        if (lane == nw - 1) smem[32] = xi;
    }
    __syncthreads();
    T res = inc - v + smem[w];
    T tot = smem[32];
    __syncthreads();
    if (total) *total = tot;
    return res;
}

// ---------------- kernel A: preparation (P0..P5 + struct sums) --------------
__global__ __launch_bounds__(TPB, 2) void prep(
    const int* __restrict__ src, const float* __restrict__ len,
    const int* __restrict__ n_atoms, int n_bond, int n_struct,
    float* __restrict__ out, int out_size) {
    __shared__ unsigned long long smLL[33];
    __shared__ int smStage[BTILE];

    int tid = threadIdx.x;
    int gtid = blockIdx.x * TPB + tid;
    const int gsize = NBLK * TPB;
    int nbt = (n_bond + BTILE - 1) / BTILE;

    int nA = 0;
    for (int s = 0; s < n_struct; s++) nA += n_atoms[s];
    int nAT = (nA + ATILE - 1) / ATILE;

    // ---- P0: zero degrees; struct bounds ----
    for (int i = gtid; i < nA; i += gsize) g_deg[i] = 0;
    if (gtid == 0) {
        int ns = n_struct < 256 ? n_struct : 256;
        int acc = 0;
        for (int s = 0; s < ns; s++) { g_bound[s] = acc; acc += n_atoms[s]; }
        g_bound[ns] = acc;
    }
    gridBarrier();

    // ---- P1: filter (mask + tile counts + run-aggregated degrees) ----
    for (int t = blockIdx.x; t < nbt; t += NBLK) {
        int base = t * BTILE + tid * BITEMS;
        unsigned nib = 0;
        int curA = -1, curC = 0;
        if (base + BITEMS <= n_bond) {
            float4 l = *(const float4*)(len + base);
            int4 s = *(const int4*)(src + base);
            float lv[4] = {l.x, l.y, l.z, l.w};
            int sv[4] = {s.x, s.y, s.z, s.w};
#pragma unroll
            for (int i = 0; i < 4; i++) {
                if (lv[i] <= CUTOFF) {
                    nib |= 1u << i;
                    if (sv[i] == curA) curC++;
                    else { if (curC) atomicAdd(&g_deg[curA], curC); curA = sv[i]; curC = 1; }
                }
            }
        } else {
            for (int i = 0; i < BITEMS; i++) {
                int b = base + i;
                if (b < n_bond && len[b] <= CUTOFF) {
                    nib |= 1u << i;
                    int a = src[b];
                    if (a == curA) curC++;
                    else { if (curC) atomicAdd(&g_deg[curA], curC); curA = a; curC = 1; }
                }
            }
        }
        if (curC) atomicAdd(&g_deg[curA], curC);
        unsigned long long word = (unsigned long long)nib << ((tid & 15) * 4);
        word |= __shfl_xor_sync(0xffffffffu, word, 1);
        word |= __shfl_xor_sync(0xffffffffu, word, 2);
        word |= __shfl_xor_sync(0xffffffffu, word, 4);
        word |= __shfl_xor_sync(0xffffffffu, word, 8);
        if ((tid & 15) == 0) g_mask[t * 32 + (tid >> 4)] = word;
        int tot;
        blockExcl<int>(__popc(nib), (int*)smLL, &tot);
        if (tid == 0) g_tileCnt[t] = tot;
    }
    gridBarrier();

    // ---- P2: block0 scans bond-tile counts ----
    if (blockIdx.x == 0) {
        int carry = 0;
        for (int b0 = 0; b0 < nbt; b0 += TPB) {
            int i = b0 + tid;
            int v = (i < nbt) ? g_tileCnt[i] : 0;
            int tot;
            int e = blockExcl<int>(v, (int*)smLL, &tot);
            if (i < nbt) g_tileOff[i] = carry + e;
            carry += tot;
        }
    }
    gridBarrier();

    // ---- P3a: scatter kept bond ids as floats ----
    for (int t = blockIdx.x; t < nbt; t += NBLK) {
        int base = t * BTILE + tid * BITEMS;
        unsigned nib = 0;
        if (base < n_bond) {
            unsigned long long w = g_mask[t * 32 + (tid >> 4)];
            nib = (unsigned)(w >> ((tid & 15) * 4)) & 0xFu;
        }
        int tot;
        int e = blockExcl<int>(__popc(nib), (int*)smLL, &tot);
#pragma unroll
        for (int i = 0; i < 4; i++)
            if ((nib >> i) & 1u) smStage[e++] = base + i;
        __syncthreads();
        int off = g_tileOff[t];
        for (int i = tid; i < tot; i += TPB) g_keptF[off + i] = (float)smStage[i];
        __syncthreads();
    }

    // ---- P3b: n_triple_ij section ----
    int offTij = out_size - n_struct - nA - n_bond;
    int nBG = (n_bond + 3) >> 2;
    for (int q = gtid; q < nBG; q += gsize) {
        int b0 = q * 4;
        unsigned long long w = g_mask[b0 >> 6];
        unsigned nib = (unsigned)(w >> (b0 & 63)) & 0xFu;
        if (b0 + 4 <= n_bond) {
            int4 s = *(const int4*)(src + b0);
            float4 r;
            r.x = (nib & 1u) ? (float)(g_deg[s.x] - 1) : 0.0f;
            r.y = (nib & 2u) ? (float)(g_deg[s.y] - 1) : 0.0f;
            r.z = (nib & 4u) ? (float)(g_deg[s.z] - 1) : 0.0f;
            r.w = (nib & 8u) ? (float)(g_deg[s.w] - 1) : 0.0f;
            __stcs((float4*)(out + offTij + b0), r);
        } else {
            for (int i = 0; b0 + i < n_bond; i++)
                out[offTij + b0 + i] =
                    ((nib >> i) & 1u) ? (float)(g_deg[src[b0 + i]] - 1) : 0.0f;
        }
    }

    // ---- P3c: per-atom-tile packed (tri<<32 | deg) sums ----
    for (int t = blockIdx.x; t < nAT; t += NBLK) {
        int base = t * ATILE + tid * AITEMS;
        unsigned long long acc = 0;
#pragma unroll
        for (int i = 0; i < 4; i++) {
            int a = base + i;
            int d = (a < nA) ? g_deg[a] : 0;
            acc += ((unsigned long long)(unsigned)(d * (d - 1)) << 32) | (unsigned)d;
        }
        unsigned long long tot;
        blockExcl<unsigned long long>(acc, smLL, &tot);
        if (tid == 0) g_atPack[t] = tot;
    }
    gridBarrier();

    // ---- P4: block0 scans atom-tile sums ----
    if (blockIdx.x == 0) {
        unsigned long long carry = 0;
        for (int b0 = 0; b0 < nAT; b0 += TPB) {
            int i = b0 + tid;
            unsigned long long v = (i < nAT) ? g_atPack[i] : 0ull;
            unsigned long long tot;
            unsigned long long e = blockExcl<unsigned long long>(v, smLL, &tot);
            if (i < nAT) g_atPackOff[i] = carry + e;
            carry += tot;
        }
        if (tid == 0) g_T = (int)(carry >> 32);
    }
    gridBarrier();

    // ---- P5: per-atom CSR offsets, triStart, n_triple_i section ----
    int offTi = out_size - n_struct - nA;
    for (int t = blockIdx.x; t < nAT; t += NBLK) {
        int base = t * ATILE + tid * AITEMS;
        int dA[4];
        unsigned long long acc = 0;
#pragma unroll
        for (int i = 0; i < 4; i++) {
            int a = base + i;
            int d = (a < nA) ? g_deg[a] : 0;
            dA[i] = d;
            acc += ((unsigned long long)(unsigned)(d * (d - 1)) << 32) | (unsigned)d;
        }
        unsigned long long e =
            blockExcl<unsigned long long>(acc, smLL, (unsigned long long*)0);
        unsigned long long run = g_atPackOff[t] + e;
#pragma unroll
        for (int i = 0; i < 4; i++) {
            int a = base + i;
            if (a < nA) {
                int d = dA[i];
                g_ab[a] = make_int2((int)(run & 0xffffffffull), d);
                g_triStart[a] = (int)(run >> 32);
                out[offTi + a] = (float)(d * (d - 1));
                run += ((unsigned long long)(unsigned)(d * (d - 1)) << 32) | (unsigned)d;
            }
        }
    }
    gridBarrier();

    // ---- P6: n_triple_s section ----
    if (gtid < n_struct) {
        int T = g_T;
        int lo = g_bound[gtid], hi = g_bound[gtid + 1];
        int vlo = (lo >= nA) ? T : g_triStart[lo];
        int vhi = (hi >= nA) ? T : g_triStart[hi];
        out[out_size - n_struct + gtid] = (float)(vhi - vlo);
    }
}

// ---------------- kernel B: tile-local pair emission (4 triples/task) --------
__global__ __launch_bounds__(EMIT_TPB) void emit(
    float* __restrict__ out, const int* __restrict__ n_atoms, int n_struct) {
    __shared__ int4 smTab[ATE];               // {off, ts, d, bits(1/(d-1))}
    __shared__ int smTS[ATE + 1];
    __shared__ unsigned char smLu[LUCAP];     // task -> local atom idx

    int nA = 0;
    for (int s = 0; s < n_struct; s++) nA += n_atoms[s];
    int T = g_T;
    int tid = threadIdx.x;
    int nTiles = (nA + ATE - 1) / ATE;

    for (int tile = blockIdx.x; tile < nTiles; tile += gridDim.x) {
        int a0 = tile * ATE;
        int nAt = min(ATE, nA - a0);
        int ts0 = g_triStart[a0];
        int ts1 = (a0 + nAt < nA) ? g_triStart[a0 + nAt] : T;
        if (ts1 <= ts0) continue;             // uniform per block: safe

        int qBase = ts0 >> 2;                 // tasks of 4 triples
        int qStart = (ts0 + 3) >> 2;
        int qEnd = (ts1 + 3) >> 2;
        bool useLu = (qEnd - qBase) <= LUCAP;

        // build table + task lookup
        for (int i = tid; i < nAt; i += EMIT_TPB) {
            int2 ab = g_ab[a0 + i];
            int ts = g_triStart[a0 + i];
            float inv = (ab.y >= 2) ? 1.0f / (float)(ab.y - 1) : 0.0f;
            smTab[i] = make_int4(ab.x, ts, ab.y, __float_as_int(inv));
            smTS[i] = ts;
            if (useLu && ab.y >= 2) {
                int tri = ab.y * (ab.y - 1);
                int u0 = ((ts + 3) >> 2) - qBase;
                int u1 = ((ts + tri + 3) >> 2) - qBase;
                unsigned w = (unsigned)i * 0x01010101u;
                int u = u0;
                for (; u < u1 && (u & 3); u++) smLu[u] = (unsigned char)i;
                for (; u + 4 <= u1; u += 4) *(unsigned*)(smLu + u) = w;
                for (; u < u1; u++) smLu[u] = (unsigned char)i;
            }
        }
        if (tid == 0) smTS[nAt] = ts1;
        __syncthreads();

        // emit tasks (4 triples each, 2 lane-contiguous float4 stores)
        for (int q = qStart + tid; q < qEnd; q += EMIT_TPB) {
            int t = q << 2;
            int i;
            if (useLu) {
                i = smLu[q - qBase];
            } else {
                int lo = 0, hi = nAt - 1;
                while (lo < hi) {
                    int m = (lo + hi + 1) >> 1;
                    if (smTS[m] <= t) lo = m; else hi = m - 1;
                }
                i = lo;
            }
            int4 tab = smTab[i];
            int off = tab.x, d = tab.z, dm1 = d - 1;
            int local = t - tab.y;
            float inv = __int_as_float(tab.w);
            int j = __float2int_rz((float)local * inv);
            int kp = local - j * dm1;
            if (kp < 0) { j--; kp += dm1; }
            else if (kp >= dm1) { j++; kp -= dm1; }

            int n = min(4, T - t);
            int ga = a0 + i;                  // global atom index of current
            float buf[8];
#pragma unroll
            for (int r = 0; r < 4; r++) {
                if (r < n) {
                    buf[2 * r] = g_keptF[off + j];
                    buf[2 * r + 1] = g_keptF[off + kp + (kp >= j)];
                    if (r + 1 < n) {
                        if (++kp == dm1) {
                            kp = 0;
                            if (++j == d) {
                                j = 0;
                                do {
                                    ga++;
                                    if (ga - a0 < nAt) {
                                        int4 tb = smTab[ga - a0];
                                        off = tb.x; d = tb.z;
                                    } else {
                                        int2 ab = g_ab[ga];
                                        off = ab.x; d = ab.y;
                                    }
                                } while (d < 2);
                                dm1 = d - 1;
                            }
                        }
                    }
                }
            }
            if (n == 4) {
                float4* o4 = (float4*)(out + (q << 3));  // 32B/lane, coalesced
                __stcs(o4 + 0, make_float4(buf[0], buf[1], buf[2], buf[3]));
                __stcs(o4 + 1, make_float4(buf[4], buf[5], buf[6], buf[7]));
            } else {
                for (int r = 0; r < n; r++) {
                    out[2 * (t + r)] = buf[2 * r];
                    out[2 * (t + r) + 1] = buf[2 * r + 1];
                }
            }
        }
        __syncthreads();
    }
}

// ---------------- launch -----------------------------------------------------
extern "C" void kernel_launch(void* const* d_in, const int* in_sizes, int n_in,
                              void* d_out, int out_size) {
    const int* src = (const int*)d_in[0];
    const float* len = (const float*)d_in[1];
    const int* n_atoms = (const int*)d_in[2];
    int n_bond = in_sizes[0];
    int n_struct = in_sizes[2];
    prep<<<NBLK, TPB>>>(src, len, n_atoms, n_bond, n_struct, (float*)d_out,
                        out_size);
    emit<<<EMIT_NBLK, EMIT_TPB>>>((float*)d_out, n_atoms, n_struct);
}

// round 17
// speedup vs baseline: 1.1538x; 1.1538x over previous
#include <cuda_runtime.h>

#define TPB 512
#define NBLK 296                      // prep: 2 CTAs/SM, all co-resident
#define BITEMS 4
#define BTILE 2048
#define AITEMS 4
#define ATILE 2048
#define MAX_BOND (1 << 22)
#define MAX_ATOM (1 << 20)
#define MAX_BT (MAX_BOND / BTILE)
#define MAX_AT0 (MAX_ATOM / ATILE)
#define CUTOFF 0.8f

#define EMIT_TPB 256
#define EMIT_NBLK 1184
#define ATE 64                        // atoms per emission tile
#define LUCAP 12288                   // task-lookup capacity (tasks)

// ---------------- scratch (static device globals; no allocations) ----------
__device__ int g_deg[MAX_ATOM];
__device__ int2 g_ab[MAX_ATOM];       // {bondOff, deg}
__device__ int g_triStart[MAX_ATOM];
__device__ float g_keptF[MAX_BOND];
__device__ unsigned long long g_mask[MAX_BOND / 64];
__device__ int g_tileCnt[MAX_BT];
__device__ int g_tileOff[MAX_BT];
__device__ unsigned long long g_atPack[MAX_AT0];
__device__ unsigned long long g_atPackOff[MAX_AT0];
__device__ int g_T;
__device__ int g_bound[260];
__device__ volatile int g_barArrive;
__device__ volatile unsigned g_barGen;

// ---------------- helpers ---------------------------------------------------
__device__ __forceinline__ void gridBarrier() {
    __syncthreads();
    if (threadIdx.x == 0) {
        __threadfence();
        unsigned gen = g_barGen;
        if (atomicAdd((int*)&g_barArrive, 1) == NBLK - 1) {
            g_barArrive = 0;
            __threadfence();
            g_barGen = gen + 1;
        } else {
            while (g_barGen == gen) __nanosleep(64);
        }
        __threadfence();
    }
    __syncthreads();
}

template <typename T>
__device__ __forceinline__ T warpIncl(T v) {
#pragma unroll
    for (int d = 1; d < 32; d <<= 1) {
        T n = __shfl_up_sync(0xffffffffu, v, d);
        if ((threadIdx.x & 31) >= d) v += n;
    }
    return v;
}

template <typename T>
__device__ __forceinline__ T blockExcl(T v, T* smem, T* total) {
    int lane = threadIdx.x & 31, w = threadIdx.x >> 5, nw = blockDim.x >> 5;
    T inc = warpIncl(v);
    if (lane == 31) smem[w] = inc;
    __syncthreads();
    if (w == 0) {
        T x = (lane < nw) ? smem[lane] : (T)0;
        T xi = warpIncl(x);
        if (lane < nw) smem[lane] = xi - x;
        if (lane == nw - 1) smem[32] = xi;
    }
    __syncthreads();
    T res = inc - v + smem[w];
    T tot = smem[32];
    __syncthreads();
    if (total) *total = tot;
    return res;
}

// ---------------- kernel A: preparation (P0..P5 + struct sums) --------------
__global__ __launch_bounds__(TPB, 2) void prep(
    const int* __restrict__ src, const float* __restrict__ len,
    const int* __restrict__ n_atoms, int n_bond, int n_struct,
    float* __restrict__ out, int out_size) {
    __shared__ unsigned long long smLL[33];
    __shared__ int smStage[BTILE];

    int tid = threadIdx.x;
    int gtid = blockIdx.x * TPB + tid;
    const int gsize = NBLK * TPB;
    int nbt = (n_bond + BTILE - 1) / BTILE;

    int nA = 0;
    for (int s = 0; s < n_struct; s++) nA += n_atoms[s];
    int nAT = (nA + ATILE - 1) / ATILE;

    // ---- P0: zero degrees; struct bounds ----
    for (int i = gtid; i < nA; i += gsize) g_deg[i] = 0;
    if (gtid == 0) {
        int ns = n_struct < 256 ? n_struct : 256;
        int acc = 0;
        for (int s = 0; s < ns; s++) { g_bound[s] = acc; acc += n_atoms[s]; }
        g_bound[ns] = acc;
    }
    gridBarrier();

    // ---- P1: filter (mask + tile counts + run-aggregated degrees) ----
    for (int t = blockIdx.x; t < nbt; t += NBLK) {
        int base = t * BTILE + tid * BITEMS;
        unsigned nib = 0;
        int curA = -1, curC = 0;
        if (base + BITEMS <= n_bond) {
            float4 l = *(const float4*)(len + base);
            int4 s = *(const int4*)(src + base);
            float lv[4] = {l.x, l.y, l.z, l.w};
            int sv[4] = {s.x, s.y, s.z, s.w};
#pragma unroll
            for (int i = 0; i < 4; i++) {
                if (lv[i] <= CUTOFF) {
                    nib |= 1u << i;
                    if (sv[i] == curA) curC++;
                    else { if (curC) atomicAdd(&g_deg[curA], curC); curA = sv[i]; curC = 1; }
                }
            }
        } else {
            for (int i = 0; i < BITEMS; i++) {
                int b = base + i;
                if (b < n_bond && len[b] <= CUTOFF) {
                    nib |= 1u << i;
                    int a = src[b];
                    if (a == curA) curC++;
                    else { if (curC) atomicAdd(&g_deg[curA], curC); curA = a; curC = 1; }
                }
            }
        }
        if (curC) atomicAdd(&g_deg[curA], curC);
        unsigned long long word = (unsigned long long)nib << ((tid & 15) * 4);
        word |= __shfl_xor_sync(0xffffffffu, word, 1);
        word |= __shfl_xor_sync(0xffffffffu, word, 2);
        word |= __shfl_xor_sync(0xffffffffu, word, 4);
        word |= __shfl_xor_sync(0xffffffffu, word, 8);
        if ((tid & 15) == 0) g_mask[t * 32 + (tid >> 4)] = word;
        int tot;
        blockExcl<int>(__popc(nib), (int*)smLL, &tot);
        if (tid == 0) g_tileCnt[t] = tot;
    }
    gridBarrier();

    // ---- P2: block0 scans bond-tile counts ----
    if (blockIdx.x == 0) {
        int carry = 0;
        for (int b0 = 0; b0 < nbt; b0 += TPB) {
            int i = b0 + tid;
            int v = (i < nbt) ? g_tileCnt[i] : 0;
            int tot;
            int e = blockExcl<int>(v, (int*)smLL, &tot);
            if (i < nbt) g_tileOff[i] = carry + e;
            carry += tot;
        }
    }
    gridBarrier();

    // ---- P3a: scatter kept bond ids as floats ----
    for (int t = blockIdx.x; t < nbt; t += NBLK) {
        int base = t * BTILE + tid * BITEMS;
        unsigned nib = 0;
        if (base < n_bond) {
            unsigned long long w = g_mask[t * 32 + (tid >> 4)];
            nib = (unsigned)(w >> ((tid & 15) * 4)) & 0xFu;
        }
        int tot;
        int e = blockExcl<int>(__popc(nib), (int*)smLL, &tot);
#pragma unroll
        for (int i = 0; i < 4; i++)
            if ((nib >> i) & 1u) smStage[e++] = base + i;
        __syncthreads();
        int off = g_tileOff[t];
        for (int i = tid; i < tot; i += TPB) g_keptF[off + i] = (float)smStage[i];
        __syncthreads();
    }

    // ---- P3b: n_triple_ij section ----
    int offTij = out_size - n_struct - nA - n_bond;
    int nBG = (n_bond + 3) >> 2;
    for (int q = gtid; q < nBG; q += gsize) {
        int b0 = q * 4;
        unsigned long long w = g_mask[b0 >> 6];
        unsigned nib = (unsigned)(w >> (b0 & 63)) & 0xFu;
        if (b0 + 4 <= n_bond) {
            int4 s = *(const int4*)(src + b0);
            float4 r;
            r.x = (nib & 1u) ? (float)(g_deg[s.x] - 1) : 0.0f;
            r.y = (nib & 2u) ? (float)(g_deg[s.y] - 1) : 0.0f;
            r.z = (nib & 4u) ? (float)(g_deg[s.z] - 1) : 0.0f;
            r.w = (nib & 8u) ? (float)(g_deg[s.w] - 1) : 0.0f;
            __stcs((float4*)(out + offTij + b0), r);
        } else {
            for (int i = 0; b0 + i < n_bond; i++)
                out[offTij + b0 + i] =
                    ((nib >> i) & 1u) ? (float)(g_deg[src[b0 + i]] - 1) : 0.0f;
        }
    }

    // ---- P3c: per-atom-tile packed (tri<<32 | deg) sums ----
    for (int t = blockIdx.x; t < nAT; t += NBLK) {
        int base = t * ATILE + tid * AITEMS;
        unsigned long long acc = 0;
#pragma unroll
        for (int i = 0; i < 4; i++) {
            int a = base + i;
            int d = (a < nA) ? g_deg[a] : 0;
            acc += ((unsigned long long)(unsigned)(d * (d - 1)) << 32) | (unsigned)d;
        }
        unsigned long long tot;
        blockExcl<unsigned long long>(acc, smLL, &tot);
        if (tid == 0) g_atPack[t] = tot;
    }
    gridBarrier();

    // ---- P4: block0 scans atom-tile sums ----
    if (blockIdx.x == 0) {
        unsigned long long carry = 0;
        for (int b0 = 0; b0 < nAT; b0 += TPB) {
            int i = b0 + tid;
            unsigned long long v = (i < nAT) ? g_atPack[i] : 0ull;
            unsigned long long tot;
            unsigned long long e = blockExcl<unsigned long long>(v, smLL, &tot);
            if (i < nAT) g_atPackOff[i] = carry + e;
            carry += tot;
        }
        if (tid == 0) g_T = (int)(carry >> 32);
    }
    gridBarrier();

    // ---- P5: per-atom CSR offsets, triStart, n_triple_i section ----
    int offTi = out_size - n_struct - nA;
    for (int t = blockIdx.x; t < nAT; t += NBLK) {
        int base = t * ATILE + tid * AITEMS;
        int dA[4];
        unsigned long long acc = 0;
#pragma unroll
        for (int i = 0; i < 4; i++) {
            int a = base + i;
            int d = (a < nA) ? g_deg[a] : 0;
            dA[i] = d;
            acc += ((unsigned long long)(unsigned)(d * (d - 1)) << 32) | (unsigned)d;
        }
        unsigned long long e =
            blockExcl<unsigned long long>(acc, smLL, (unsigned long long*)0);
        unsigned long long run = g_atPackOff[t] + e;
#pragma unroll
        for (int i = 0; i < 4; i++) {
            int a = base + i;
            if (a < nA) {
                int d = dA[i];
                g_ab[a] = make_int2((int)(run & 0xffffffffull), d);
                g_triStart[a] = (int)(run >> 32);
                out[offTi + a] = (float)(d * (d - 1));
                run += ((unsigned long long)(unsigned)(d * (d - 1)) << 32) | (unsigned)d;
            }
        }
    }
    gridBarrier();

    // ---- P6: n_triple_s section ----
    if (gtid < n_struct) {
        int T = g_T;
        int lo = g_bound[gtid], hi = g_bound[gtid + 1];
        int vlo = (lo >= nA) ? T : g_triStart[lo];
        int vhi = (hi >= nA) ? T : g_triStart[hi];
        out[out_size - n_struct + gtid] = (float)(vhi - vlo);
    }
}

// ---------------- kernel B: tile-local pair emission (2 triples/task) --------
__global__ __launch_bounds__(EMIT_TPB) void emit(
    float* __restrict__ out, const int* __restrict__ n_atoms, int n_struct) {
    __shared__ int4 smTab[ATE];               // {off, ts, d, bits(1/(d-1))}
    __shared__ int smTS[ATE + 1];
    __shared__ unsigned char smLu[LUCAP];     // task -> local atom idx

    int nA = 0;
    for (int s = 0; s < n_struct; s++) nA += n_atoms[s];
    int T = g_T;
    int tid = threadIdx.x;
    int nTiles = (nA + ATE - 1) / ATE;

    for (int tile = blockIdx.x; tile < nTiles; tile += gridDim.x) {
        int a0 = tile * ATE;
        int nAt = min(ATE, nA - a0);
        int ts0 = g_triStart[a0];
        int ts1 = (a0 + nAt < nA) ? g_triStart[a0 + nAt] : T;
        if (ts1 <= ts0) continue;             // uniform per block: safe

        int qBase = ts0 >> 1;
        int qStart = (ts0 + 1) >> 1;
        int qEnd = (ts1 + 1) >> 1;
        bool useLu = (qEnd - qBase) <= LUCAP;

        // build table + lookup
        for (int i = tid; i < nAt; i += EMIT_TPB) {
            int2 ab = g_ab[a0 + i];
            int ts = g_triStart[a0 + i];
            float inv = (ab.y >= 2) ? 1.0f / (float)(ab.y - 1) : 0.0f;
            smTab[i] = make_int4(ab.x, ts, ab.y, __float_as_int(inv));
            smTS[i] = ts;
            if (useLu && ab.y >= 2) {
                int tri = ab.y * (ab.y - 1);
                int u0 = ((ts + 1) >> 1) - qBase;
                int u1 = ((ts + tri + 1) >> 1) - qBase;
                unsigned w = (unsigned)i * 0x01010101u;
                int u = u0;
                for (; u < u1 && (u & 3); u++) smLu[u] = (unsigned char)i;
                for (; u + 4 <= u1; u += 4) *(unsigned*)(smLu + u) = w;
                for (; u < u1; u++) smLu[u] = (unsigned char)i;
            }
        }
        if (tid == 0) smTS[nAt] = ts1;
        __syncthreads();

        // emit tasks (2 triples each, lane-contiguous float4 stores)
        for (int q = qStart + tid; q < qEnd; q += EMIT_TPB) {
            int t = q << 1;
            int i;
            if (useLu) {
                i = smLu[q - qBase];
            } else {
                int lo = 0, hi = nAt - 1;
                while (lo < hi) {
                    int m = (lo + hi + 1) >> 1;
                    if (smTS[m] <= t) lo = m; else hi = m - 1;
                }
                i = lo;
            }
            int4 tab = smTab[i];
            int off = tab.x, d = tab.z, dm1 = d - 1;
            int local = t - tab.y;
            float inv = __int_as_float(tab.w);
            int j = __float2int_rz((float)local * inv);
            int kp = local - j * dm1;
            if (kp < 0) { j--; kp += dm1; }
            else if (kp >= dm1) { j++; kp -= dm1; }
            float4 v;
            v.x = g_keptF[off + j];
            v.y = g_keptF[off + kp + (kp >= j)];
            if (t + 1 < T) {
                int off2 = off, j2 = j, kp2 = kp + 1;
                if (kp2 == dm1) {
                    kp2 = 0; j2 = j + 1;
                    if (j2 == d) {
                        j2 = 0;
                        int i2 = i + 1;
                        while (i2 < nAt && smTab[i2].z < 2) i2++;
                        if (i2 < nAt) {
                            off2 = smTab[i2].x;
                        } else {
                            int aa = a0 + nAt;
                            int2 ab2 = g_ab[aa];
                            while (ab2.y < 2) { aa++; ab2 = g_ab[aa]; }
                            off2 = ab2.x;
                        }
                    }
                }
                v.z = g_keptF[off2 + j2];
                v.w = g_keptF[off2 + kp2 + (kp2 >= j2)];
                __stcs((float4*)(out + (q << 2)), v);
            } else {
                *(float2*)(out + (q << 2)) = make_float2(v.x, v.y);
            }
        }
        __syncthreads();
    }
}

// ---------------- launch -----------------------------------------------------
extern "C" void kernel_launch(void* const* d_in, const int* in_sizes, int n_in,
                              void* d_out, int out_size) {
    const int* src = (const int*)d_in[0];
    const float* len = (const float*)d_in[1];
    const int* n_atoms = (const int*)d_in[2];
    int n_bond = in_sizes[0];
    int n_struct = in_sizes[2];
    prep<<<NBLK, TPB>>>(src, len, n_atoms, n_bond, n_struct, (float*)d_out,
                        out_size);
    emit<<<EMIT_NBLK, EMIT_TPB>>>((float*)d_out, n_atoms, n_struct);
}